// round 1
// baseline (speedup 1.0000x reference)
#include <cuda_runtime.h>
#include <cuda_bf16.h>
#include <cstddef>

// Problem constants
#define NB   64
#define NIC  128
#define NOC  256
#define NHW  56
#define NDG  4

// Tiling
#define OC_T 64      // output channels per block
#define SH   4       // output rows per block
#define SW   28      // output cols per block
#define ICC  8       // input-channel chunk
#define NTHREADS 224 // 8 oc-groups x 28 spatial threads

// Premultiplied masked weights, layout [d][ic][tap][oc]  (oc contiguous)
__device__ float g_w[NDG * NIC * 9 * NOC];

// ---------------------------------------------------------------------------
// Prep: g_w[d][ic][tap][oc] = base[oc][ic][tap] * mask[d][ic][tap]
// ---------------------------------------------------------------------------
__global__ void prep_weights_kernel(const float* __restrict__ base,
                                    const float* __restrict__ mask) {
    int e = blockIdx.x * blockDim.x + threadIdx.x;
    const int total = NDG * NIC * 9 * NOC;
    if (e >= total) return;
    int oc  = e % NOC;
    int t2  = e / NOC;         // (d*128 + ic)*9 + tap
    int tap = t2 % 9;
    int t3  = t2 / 9;          // d*128 + ic
    int ic  = t3 % NIC;
    int d   = t3 / NIC;
    g_w[e] = base[(oc * NIC + ic) * 9 + tap] * mask[(d * NIC + ic) * 9 + tap];
}

// ---------------------------------------------------------------------------
// Direct tiled conv, fp32. Block = (b, octile, spatial tile 4x28).
// Thread: ocg = tid%8 (handles oc = ocg+8j, j=0..7), tw = tid/8 (one w col,
// 4 h rows). 32 accumulators/thread.
// ---------------------------------------------------------------------------
__global__ __launch_bounds__(NTHREADS, 4)
void adaconv_kernel(const float* __restrict__ x,
                    const int*   __restrict__ label,
                    float*       __restrict__ out) {
    __shared__ float xs[ICC][SH + 2][32];      // input patch, padded rows
    __shared__ float ws[ICC][9][OC_T];         // weights

    const int b      = blockIdx.z;
    const int octile = blockIdx.y;
    const int sp     = blockIdx.x;             // 0..27
    const int h0     = (sp >> 1) * SH;
    const int w0     = (sp & 1) * SW;

    const int tid = threadIdx.x;
    const int ocg = tid & 7;                   // 0..7
    const int tw  = tid >> 3;                  // 0..27

    int d = label[b];
    d = (d < 0) ? 0 : (d > NDG - 1 ? NDG - 1 : d);

    const float* __restrict__ wg = g_w + (size_t)d * NIC * 9 * NOC + octile * OC_T;
    const float* __restrict__ xg = x + (size_t)b * NIC * NHW * NHW;

    float acc[4][8];
#pragma unroll
    for (int r = 0; r < 4; ++r)
#pragma unroll
        for (int j = 0; j < 8; ++j) acc[r][j] = 0.f;

    for (int icc = 0; icc < NIC / ICC; ++icc) {
        __syncthreads();

        // ---- load input patch: ICC x 6 x 30 (zero-padded halo) ----
        for (int idx = tid; idx < ICC * 6 * 30; idx += NTHREADS) {
            int ic  = idx / 180;
            int rem = idx % 180;
            int hh  = rem / 30;
            int ww  = rem % 30;
            int gh  = h0 - 1 + hh;
            int gw  = w0 - 1 + ww;
            float v = 0.f;
            if (gh >= 0 && gh < NHW && gw >= 0 && gw < NHW)
                v = xg[(icc * ICC + ic) * NHW * NHW + gh * NHW + gw];
            xs[ic][hh][ww] = v;
        }

        // ---- load weights: ws[ic][tap][oc], 256B-coalesced from g_w ----
        for (int idx = tid; idx < ICC * 9 * OC_T; idx += NTHREADS) {
            int oc  = idx & 63;
            int t2  = idx >> 6;
            int tap = t2 % 9;
            int ic  = t2 / 9;
            ws[ic][tap][oc] = wg[((icc * ICC + ic) * 9 + tap) * NOC + oc];
        }

        __syncthreads();

        // ---- compute ----
#pragma unroll 2
        for (int ic = 0; ic < ICC; ++ic) {
#pragma unroll
            for (int kh = 0; kh < 3; ++kh) {
#pragma unroll
                for (int kw = 0; kw < 3; ++kw) {
                    float xv0 = xs[ic][0 + kh][tw + kw];
                    float xv1 = xs[ic][1 + kh][tw + kw];
                    float xv2 = xs[ic][2 + kh][tw + kw];
                    float xv3 = xs[ic][3 + kh][tw + kw];
#pragma unroll
                    for (int j = 0; j < 8; ++j) {
                        float wv = ws[ic][kh * 3 + kw][ocg + 8 * j];
                        acc[0][j] += xv0 * wv;
                        acc[1][j] += xv1 * wv;
                        acc[2][j] += xv2 * wv;
                        acc[3][j] += xv3 * wv;
                    }
                }
            }
        }
    }

    // ---- write output ----
    float* __restrict__ og = out + ((size_t)b * NOC + octile * OC_T) * NHW * NHW;
#pragma unroll
    for (int j = 0; j < 8; ++j) {
        int oc = ocg + 8 * j;
#pragma unroll
        for (int r = 0; r < 4; ++r) {
            og[oc * NHW * NHW + (h0 + r) * NHW + (w0 + tw)] = acc[r][j];
        }
    }
}

// ---------------------------------------------------------------------------
// Launch
// ---------------------------------------------------------------------------
extern "C" void kernel_launch(void* const* d_in, const int* in_sizes, int n_in,
                              void* d_out, int out_size) {
    // Identify inputs by element count (robust to metadata ordering):
    //   x = 64*128*56*56 = 25690112, label = 64,
    //   base = 256*128*9 = 294912,  mask = 4*128*9 = 4608, epoch = 1 (ignored)
    const float* x     = nullptr;
    const int*   label = nullptr;
    const float* base  = nullptr;
    const float* mask  = nullptr;
    for (int i = 0; i < n_in; ++i) {
        switch (in_sizes[i]) {
            case 25690112: x     = (const float*)d_in[i]; break;
            case 64:       label = (const int*)  d_in[i]; break;
            case 294912:   base  = (const float*)d_in[i]; break;
            case 4608:     mask  = (const float*)d_in[i]; break;
            default: break; // epoch scalar etc.
        }
    }
    // Fallback to positional order if sizes didn't match
    if (!x     && n_in > 0) x     = (const float*)d_in[0];
    if (!label && n_in > 1) label = (const int*)  d_in[1];
    if (!base  && n_in > 2) base  = (const float*)d_in[2];
    if (!mask  && n_in > 3) mask  = (const float*)d_in[3];

    float* out = (float*)d_out;

    // Prep masked weights into g_w
    {
        const int total = NDG * NIC * 9 * NOC;
        int threads = 256;
        int blocks  = (total + threads - 1) / threads;
        prep_weights_kernel<<<blocks, threads>>>(base, mask);
    }

    // Conv
    {
        dim3 grid(28, NOC / OC_T, NB);   // (spatial tiles, oc tiles, batch)
        adaconv_kernel<<<grid, NTHREADS>>>(x, label, out);
    }
}